// round 15
// baseline (speedup 1.0000x reference)
#include <cuda_runtime.h>

#define NB 16
#define CH 256
#define KS 6
#define MS 22
#define HO 17
#define OUT_PER_N (HO*HO)          // 289
#define TOT_OUT (NB*OUT_PER_N)     // 4624
#define CPB 16                     // channels per block
#define NCHUNK (CH/CPB)            // 16
#define RS 23                      // smem row stride
#define CSTR 507                   // channel tile stride
#define ZSTR 37                    // z tile stride
#define TPB 544                    // 16 cl * 17 oy * 2 halves
#define OXW 9
#define XCOLS 14
#define IDX4 (TOT_OUT/4)           // 1156 float4 columns
#define NL 4                       // ceil(1936/544) front-batched loads/thread

// partials: [chunk][idx], 16B-aligned
__device__ float4 g_p4[NCHUNK * IDX4];
__device__ float4 g_mean4[IDX4];

__device__ __forceinline__ float fsqrt_fast(float a) {
    float r; asm("sqrt.approx.f32 %0, %1;" : "=f"(r) : "f"(a)); return r;
}

// ---------------------------------------------------------------------------
// Kernel 1: per-(chunk, n) sliding correlation.
// thread = (cl, oy, ox-half): 1 output row x 9 cols, 324 FMA, ~48 regs.
// 544 threads/block -> 17 warps; grid 256 -> ~29 warps/SM resident.
// ---------------------------------------------------------------------------
__global__ __launch_bounds__(TPB, 2) void corr_kernel(
    const float* __restrict__ z, const float* __restrict__ x,
    const float* __restrict__ w)
{
    __shared__ float xs[CPB * CSTR];      // 8112 floats; reused as reduce scratch
    __shared__ float zs[CPB * ZSTR];      // 592

    const int chunk = blockIdx.x;
    const int n     = blockIdx.y;
    const int t     = threadIdx.x;

    // --- phase A: front-batched gmem loads (4 independent LDG.128) ---
    const float4* xg4 = (const float4*)(x + (size_t)(n * CH + chunk * CPB) * (MS * MS));
    float4 v[NL];
#pragma unroll
    for (int i = 0; i < NL; i++) {
        int e4 = t + i * TPB;
        if (e4 < CPB * 121) v[i] = xg4[e4];
    }
    const float* zg = z + (size_t)(n * CH + chunk * CPB) * (KS * KS);
    float zv0 = 0.f, zv1 = 0.f;
    {
        int e0 = t, e1 = t + TPB;
        if (e0 < CPB * KS * KS) zv0 = zg[e0];
        if (e1 < CPB * KS * KS) zv1 = zg[e1];
    }

    // --- phase B: sqrt + smem stores ---
#pragma unroll
    for (int i = 0; i < NL; i++) {
        int e4 = t + i * TPB;
        if (e4 < CPB * 121) {
            unsigned cl   = (unsigned)e4 / 121u;
            unsigned rem4 = (unsigned)e4 - cl * 121u;
            unsigned r0   = (2u * rem4) / 11u;        // (4*rem4)/22
            unsigned c0   = 4u * rem4 - 22u * r0;     // even, 0..20
            unsigned base = cl * CSTR + r0 * RS + c0;
            unsigned p    = (c0 == 20u) ? 1u : 0u;    // wrap shifts exactly +1
            xs[base + 0]     = fsqrt_fast(v[i].x);
            xs[base + 1]     = fsqrt_fast(v[i].y);
            xs[base + 2 + p] = fsqrt_fast(v[i].z);
            xs[base + 3 + p] = fsqrt_fast(v[i].w);
        }
    }
    {
        int e0 = t, e1 = t + TPB;
        if (e0 < CPB * KS * KS) {
            unsigned cl = (unsigned)e0 / 36u, k = (unsigned)e0 - cl * 36u;
            zs[cl * ZSTR + k] = fsqrt_fast(zv0) * w[chunk * CPB + cl];
        }
        if (e1 < CPB * KS * KS) {
            unsigned cl = (unsigned)e1 / 36u, k = (unsigned)e1 - cl * 36u;
            zs[cl * ZSTR + k] = fsqrt_fast(zv1) * w[chunk * CPB + cl];
        }
    }
    __syncthreads();

    // --- compute: thread = (cl, oy, half); 9 sliding outputs on one row ---
    const int cl   = t & 15;
    const int rest = t >> 4;              // 0..33
    const int oy   = rest % HO;
    const int half = rest / HO;           // 0 or 1
    const int ox0  = half * OXW;          // 0 or 9
    const float* xb = &xs[cl * CSTR + ox0];
    const float* zb = &zs[cl * ZSTR];

    float acc[OXW];
#pragma unroll
    for (int i = 0; i < OXW; i++) acc[i] = 0.f;

#pragma unroll
    for (int k1 = 0; k1 < KS; k1++) {
        float xr[XCOLS];
        // half==1, j==13 reads the pad slot: feeds only acc[8], discarded below.
#pragma unroll
        for (int j = 0; j < XCOLS; j++) xr[j] = xb[(oy + k1) * RS + j];
#pragma unroll
        for (int k2 = 0; k2 < KS; k2++) {
            float zv = zb[k1 * KS + k2];          // conflict-free LDS (37cl mod 32)
#pragma unroll
            for (int i = 0; i < OXW; i++)
                acc[i] = fmaf(xr[i + k2], zv, acc[i]);
        }
    }

    // --- block reduce over 16 channel lanes (fixed order -> deterministic) ---
    __syncthreads();
    float* scratch = xs;                  // 16 * 289 = 4624 floats
    const int nox = (half == 0) ? OXW : (OXW - 1);
#pragma unroll
    for (int i = 0; i < OXW; i++)
        if (i < nox) scratch[cl * OUT_PER_N + oy * HO + ox0 + i] = acc[i];
    __syncthreads();

    float* gp = (float*)g_p4;             // [chunk][4624]
    for (int idx = t; idx < OUT_PER_N; idx += TPB) {
        float s = 0.f;
#pragma unroll
        for (int c2 = 0; c2 < CPB; c2++) s += scratch[c2 * OUT_PER_N + idx];
        gp[chunk * TOT_OUT + n * OUT_PER_N + idx] = s;
    }
}

// ---------------------------------------------------------------------------
// Kernel 2: chunk reduce, ONE gmem load per thread, smem tree over chunks.
// ---------------------------------------------------------------------------
#define RBT 512
#define RBCOLS 32
#define RBG ((IDX4 + RBCOLS - 1) / RBCOLS)     // 37 blocks
__global__ __launch_bounds__(RBT) void chunk_reduce()
{
    __shared__ float4 sp[NCHUNK][RBCOLS];      // 8 KB
    const int t     = threadIdx.x;
    const int chunk = t >> 5;                  // 0..15
    const int lane  = t & 31;
    const int idx4  = blockIdx.x * RBCOLS + lane;

    float4 p = make_float4(0.f, 0.f, 0.f, 0.f);
    if (idx4 < IDX4) p = g_p4[chunk * IDX4 + idx4];
    sp[chunk][lane] = p;
    __syncthreads();

#pragma unroll
    for (int s = NCHUNK / 2; s >= 1; s >>= 1) {
        if (chunk < s) {
            float4 a = sp[chunk][lane];
            float4 b = sp[chunk + s][lane];
            a.x += b.x; a.y += b.y; a.z += b.z; a.w += b.w;
            sp[chunk][lane] = a;
        }
        __syncthreads();
    }
    if (chunk == 0 && idx4 < IDX4) {
        float4 a = sp[0][lane];
        a.x *= (1.f/36.f); a.y *= (1.f/36.f); a.z *= (1.f/36.f); a.w *= (1.f/36.f);
        g_mean4[idx4] = a;
    }
}

// ---------------------------------------------------------------------------
// Kernel 3: single-block BatchNorm over 4624 values (18.5 KB, MLP=3).
// ---------------------------------------------------------------------------
#define BNT 512
#define VPT 3                                  // 512*3 >= 1156
__global__ __launch_bounds__(BNT) void finalize(
    float* __restrict__ out,
    const float* __restrict__ bw, const float* __restrict__ bb)
{
    __shared__ float sred[BNT];
    __shared__ float s_mu, s_scale;
    const int t = threadIdx.x;

    float4 v[VPT];
#pragma unroll
    for (int g = 0; g < VPT; g++) {
        int i4 = t + g * BNT;
        v[g] = (i4 < IDX4) ? g_mean4[i4] : make_float4(0.f,0.f,0.f,0.f);
    }
    float lsum = 0.f;
#pragma unroll
    for (int g = 0; g < VPT; g++)
        lsum += (v[g].x + v[g].y) + (v[g].z + v[g].w);

    sred[t] = lsum; __syncthreads();
    for (int sz = BNT / 2; sz > 0; sz >>= 1) { if (t < sz) sred[t] += sred[t + sz]; __syncthreads(); }
    if (t == 0) s_mu = sred[0] / (float)TOT_OUT;
    __syncthreads();
    const float mu = s_mu;

    float lss = 0.f;
#pragma unroll
    for (int g = 0; g < VPT; g++) {
        int i4 = t + g * BNT;
        if (i4 < IDX4) {
            float dx = v[g].x - mu, dy = v[g].y - mu, dz = v[g].z - mu, dw = v[g].w - mu;
            lss += (dx*dx + dy*dy) + (dz*dz + dw*dw);
        }
    }
    sred[t] = lss; __syncthreads();
    for (int sz = BNT / 2; sz > 0; sz >>= 1) { if (t < sz) sred[t] += sred[t + sz]; __syncthreads(); }
    if (t == 0) s_scale = rsqrtf(sred[0] / (float)TOT_OUT + 1e-5f) * bw[0];
    __syncthreads();
    const float scale = s_scale;
    const float bias  = bb[0];

#pragma unroll
    for (int g = 0; g < VPT; g++) {
        int i4 = t + g * BNT;
        if (i4 < IDX4) {
            float4 o;
            o.x = (v[g].x - mu) * scale + bias;
            o.y = (v[g].y - mu) * scale + bias;
            o.z = (v[g].z - mu) * scale + bias;
            o.w = (v[g].w - mu) * scale + bias;
            ((float4*)out)[i4] = o;
        }
    }
}

extern "C" void kernel_launch(void* const* d_in, const int* in_sizes, int n_in,
                              void* d_out, int out_size)
{
    const float* z  = (const float*)d_in[0];
    const float* x  = (const float*)d_in[1];
    const float* w  = (const float*)d_in[2];
    const float* bw = (const float*)d_in[3];
    const float* bb = (const float*)d_in[4];

    int first_one = -1;
    for (int i = 0; i < n_in; i++) {
        if (in_sizes[i] == NB * CH * KS * KS)      z = (const float*)d_in[i];
        else if (in_sizes[i] == NB * CH * MS * MS) x = (const float*)d_in[i];
        else if (in_sizes[i] == CH)                w = (const float*)d_in[i];
        else if (in_sizes[i] == 1) {
            if (first_one < 0) { bw = (const float*)d_in[i]; first_one = i; }
            else                 bb = (const float*)d_in[i];
        }
    }

    dim3 grid(NCHUNK, NB);                       // 16 x 16 = 256 blocks
    corr_kernel<<<grid, TPB>>>(z, x, w);
    chunk_reduce<<<RBG, RBT>>>();                // 37 blocks, pure parallel
    finalize<<<1, BNT>>>((float*)d_out, bw, bb);
}

// round 16
// speedup vs baseline: 1.1080x; 1.1080x over previous
#include <cuda_runtime.h>

#define NB 16
#define CH 256
#define KS 6
#define MS 22
#define HO 17
#define OUT_PER_N (HO*HO)          // 289
#define TOT_OUT (NB*OUT_PER_N)     // 4624
#define CPB 16                     // channels per block
#define NCHUNK (CH/CPB)            // 16
#define RS 23                      // smem row stride (odd)
#define CSTR 514                   // tile stride; 514 mod 32 == 2 -> cl on EVEN banks,
                                   // half-warp offset (odd*23 or 25) -> ODD banks: conflict-free
#define ZSTR 37                    // z tile stride
#define TPB 544                    // 16 cl * 17 oy * 2 halves
#define OXW 9
#define XCOLS 14
#define IDX4 (TOT_OUT/4)           // 1156 float4 columns
#define NL 4                       // ceil(1936/544) front-batched loads/thread

// partials: [chunk][idx], 16B-aligned
__device__ float4 g_p4[NCHUNK * IDX4];
__device__ float4 g_mean4[IDX4];
__device__ int    g_count = 0;     // returns to 0 every launch

__device__ __forceinline__ float fsqrt_fast(float a) {
    float r; asm("sqrt.approx.f32 %0, %1;" : "=f"(r) : "f"(a)); return r;
}
__device__ __forceinline__ float4 ldcg4(const float4* p) {
    float4 v;
    asm volatile("ld.global.cg.v4.f32 {%0,%1,%2,%3}, [%4];"
                 : "=f"(v.x), "=f"(v.y), "=f"(v.z), "=f"(v.w) : "l"(p));
    return v;
}

// ---------------------------------------------------------------------------
// Kernel 1: per-(chunk, n) sliding correlation.
// thread = (cl, oy, ox-half): 1 row x 9 cols; conflict-free LDS by parity:
// even banks carry the 16 channels, odd banks the second half-warp.
// ---------------------------------------------------------------------------
__global__ __launch_bounds__(TPB, 2) void corr_kernel(
    const float* __restrict__ z, const float* __restrict__ x,
    const float* __restrict__ w)
{
    __shared__ float xs[CPB * CSTR];      // 8224 floats; reused as reduce scratch
    __shared__ float zs[CPB * ZSTR];      // 592

    const int chunk = blockIdx.x;
    const int n     = blockIdx.y;
    const int t     = threadIdx.x;

    // --- phase A: front-batched gmem loads (4 independent LDG.128) ---
    const float4* xg4 = (const float4*)(x + (size_t)(n * CH + chunk * CPB) * (MS * MS));
    float4 v[NL];
#pragma unroll
    for (int i = 0; i < NL; i++) {
        int e4 = t + i * TPB;
        if (e4 < CPB * 121) v[i] = xg4[e4];
    }
    const float* zg = z + (size_t)(n * CH + chunk * CPB) * (KS * KS);
    float zv0 = 0.f, zv1 = 0.f;
    {
        int e0 = t, e1 = t + TPB;
        if (e0 < CPB * KS * KS) zv0 = zg[e0];
        if (e1 < CPB * KS * KS) zv1 = zg[e1];
    }

    // --- phase B: sqrt + smem stores ---
#pragma unroll
    for (int i = 0; i < NL; i++) {
        int e4 = t + i * TPB;
        if (e4 < CPB * 121) {
            unsigned cl   = (unsigned)e4 / 121u;
            unsigned rem4 = (unsigned)e4 - cl * 121u;
            unsigned r0   = (2u * rem4) / 11u;        // (4*rem4)/22
            unsigned c0   = 4u * rem4 - 22u * r0;     // even, 0..20
            unsigned base = cl * CSTR + r0 * RS + c0;
            unsigned p    = (c0 == 20u) ? 1u : 0u;    // wrap shifts exactly +1
            xs[base + 0]     = fsqrt_fast(v[i].x);
            xs[base + 1]     = fsqrt_fast(v[i].y);
            xs[base + 2 + p] = fsqrt_fast(v[i].z);
            xs[base + 3 + p] = fsqrt_fast(v[i].w);
        }
    }
    {
        int e0 = t, e1 = t + TPB;
        if (e0 < CPB * KS * KS) {
            unsigned cl = (unsigned)e0 / 36u, k = (unsigned)e0 - cl * 36u;
            zs[cl * ZSTR + k] = fsqrt_fast(zv0) * w[chunk * CPB + cl];
        }
        if (e1 < CPB * KS * KS) {
            unsigned cl = (unsigned)e1 / 36u, k = (unsigned)e1 - cl * 36u;
            zs[cl * ZSTR + k] = fsqrt_fast(zv1) * w[chunk * CPB + cl];
        }
    }
    __syncthreads();

    // --- compute: thread = (cl, oy, half); 9 sliding outputs on one row ---
    const int cl   = t & 15;
    const int rest = t >> 4;              // 0..33
    const int oy   = rest % HO;
    const int half = rest / HO;           // 0 or 1
    const int ox0  = half * OXW;          // 0 or 9
    const float* xb = &xs[cl * CSTR + ox0];
    const float* zb = &zs[cl * ZSTR];

    float acc[OXW];
#pragma unroll
    for (int i = 0; i < OXW; i++) acc[i] = 0.f;

#pragma unroll
    for (int k1 = 0; k1 < KS; k1++) {
        float xr[XCOLS];
        // half==1, j==13 reads a never-written spare word inside the tile:
        // it feeds only acc[8], which half 1 discards below.
#pragma unroll
        for (int j = 0; j < XCOLS; j++) xr[j] = xb[(oy + k1) * RS + j];
#pragma unroll
        for (int k2 = 0; k2 < KS; k2++) {
            float zv = zb[k1 * KS + k2];          // same-address broadcast per cl
#pragma unroll
            for (int i = 0; i < OXW; i++)
                acc[i] = fmaf(xr[i + k2], zv, acc[i]);
        }
    }

    // --- block reduce over 16 channel lanes (fixed order -> deterministic) ---
    __syncthreads();
    float* scratch = xs;                  // 16 * 289 = 4624 floats
    const int nox = (half == 0) ? OXW : (OXW - 1);
#pragma unroll
    for (int i = 0; i < OXW; i++)
        if (i < nox) scratch[cl * OUT_PER_N + oy * HO + ox0 + i] = acc[i];
    __syncthreads();

    float* gp = (float*)g_p4;             // [chunk][4624]
    for (int idx = t; idx < OUT_PER_N; idx += TPB) {
        float s = 0.f;
#pragma unroll
        for (int c2 = 0; c2 < CPB; c2++) s += scratch[c2 * OUT_PER_N + idx];
        gp[chunk * TOT_OUT + n * OUT_PER_N + idx] = s;
    }
}

// ---------------------------------------------------------------------------
// Kernel 2 (fused, R13 winner): chunk reduce, one gmem load/thread, smem tree;
// last block (ticket) runs the 512-thread BatchNorm tail.
// ---------------------------------------------------------------------------
#define RBT 512
#define RBCOLS 32
#define RBG ((IDX4 + RBCOLS - 1) / RBCOLS)     // 37 blocks
#define VPT 3                                  // tail: 512*3 >= 1156
__global__ __launch_bounds__(RBT) void reduce_bn(
    float* __restrict__ out,
    const float* __restrict__ bw, const float* __restrict__ bb)
{
    __shared__ float4 sp[NCHUNK][RBCOLS];      // 8 KB; reused by tail
    const int t     = threadIdx.x;
    const int chunk = t >> 5;                  // 0..15
    const int lane  = t & 31;
    const int idx4  = blockIdx.x * RBCOLS + lane;

    float4 p = make_float4(0.f, 0.f, 0.f, 0.f);
    if (idx4 < IDX4) p = g_p4[chunk * IDX4 + idx4];
    sp[chunk][lane] = p;
    __syncthreads();

#pragma unroll
    for (int s = NCHUNK / 2; s >= 1; s >>= 1) {
        if (chunk < s) {
            float4 a = sp[chunk][lane];
            float4 b = sp[chunk + s][lane];
            a.x += b.x; a.y += b.y; a.z += b.z; a.w += b.w;
            sp[chunk][lane] = a;
        }
        __syncthreads();
    }
    if (chunk == 0 && idx4 < IDX4) {
        float4 a = sp[0][lane];
        a.x *= (1.f/36.f); a.y *= (1.f/36.f); a.z *= (1.f/36.f); a.w *= (1.f/36.f);
        g_mean4[idx4] = a;
    }

    // --- last-block-done ticket ---
    __threadfence();
    __syncthreads();
    __shared__ bool amLast;
    if (t == 0) amLast = (atomicAdd(&g_count, 1) == RBG - 1);
    __syncthreads();
    if (!amLast) return;

    // --- BatchNorm tail: 512 threads, 3 front-batched loads each ---
    float* sred = (float*)sp;                  // reuse smem
    __shared__ float s_mu, s_scale;

    float4 v[VPT];
#pragma unroll
    for (int g = 0; g < VPT; g++) {
        int i4 = t + g * RBT;
        v[g] = (i4 < IDX4) ? ldcg4(&g_mean4[i4]) : make_float4(0.f,0.f,0.f,0.f);
    }
    float lsum = 0.f;
#pragma unroll
    for (int g = 0; g < VPT; g++)
        lsum += (v[g].x + v[g].y) + (v[g].z + v[g].w);

    sred[t] = lsum; __syncthreads();
    for (int sz = RBT / 2; sz > 0; sz >>= 1) { if (t < sz) sred[t] += sred[t + sz]; __syncthreads(); }
    if (t == 0) s_mu = sred[0] / (float)TOT_OUT;
    __syncthreads();
    const float mu = s_mu;

    float lss = 0.f;
#pragma unroll
    for (int g = 0; g < VPT; g++) {
        int i4 = t + g * RBT;
        if (i4 < IDX4) {
            float dx = v[g].x - mu, dy = v[g].y - mu, dz = v[g].z - mu, dw = v[g].w - mu;
            lss += (dx*dx + dy*dy) + (dz*dz + dw*dw);
        }
    }
    sred[t] = lss; __syncthreads();
    for (int sz = RBT / 2; sz > 0; sz >>= 1) { if (t < sz) sred[t] += sred[t + sz]; __syncthreads(); }
    if (t == 0) s_scale = rsqrtf(sred[0] / (float)TOT_OUT + 1e-5f) * bw[0];
    __syncthreads();
    const float scale = s_scale;
    const float bias  = bb[0];

#pragma unroll
    for (int g = 0; g < VPT; g++) {
        int i4 = t + g * RBT;
        if (i4 < IDX4) {
            float4 o;
            o.x = (v[g].x - mu) * scale + bias;
            o.y = (v[g].y - mu) * scale + bias;
            o.z = (v[g].z - mu) * scale + bias;
            o.w = (v[g].w - mu) * scale + bias;
            ((float4*)out)[i4] = o;
        }
    }

    if (t == 0) g_count = 0;              // reset for next graph replay
}

extern "C" void kernel_launch(void* const* d_in, const int* in_sizes, int n_in,
                              void* d_out, int out_size)
{
    const float* z  = (const float*)d_in[0];
    const float* x  = (const float*)d_in[1];
    const float* w  = (const float*)d_in[2];
    const float* bw = (const float*)d_in[3];
    const float* bb = (const float*)d_in[4];

    int first_one = -1;
    for (int i = 0; i < n_in; i++) {
        if (in_sizes[i] == NB * CH * KS * KS)      z = (const float*)d_in[i];
        else if (in_sizes[i] == NB * CH * MS * MS) x = (const float*)d_in[i];
        else if (in_sizes[i] == CH)                w = (const float*)d_in[i];
        else if (in_sizes[i] == 1) {
            if (first_one < 0) { bw = (const float*)d_in[i]; first_one = i; }
            else                 bb = (const float*)d_in[i];
        }
    }

    dim3 grid(NCHUNK, NB);                       // 16 x 16 = 256 blocks
    corr_kernel<<<grid, TPB>>>(z, x, w);
    reduce_bn<<<RBG, RBT>>>((float*)d_out, bw, bb);
}